// round 10
// baseline (speedup 1.0000x reference)
#include <cuda_runtime.h>
#include <stdint.h>
#include <math.h>

#define BATCH 32
#define CHAN  256
#define HH    56
#define WW    56
#define S     (HH*WW)        // 3136
#define S4    (S/4)          // 784
#define RNUM  1568           // removed_num = round(3136*0.5)

// scratch (no cudaMalloc allowed)
__device__ __align__(16) float g_pool_max[BATCH*S];
__device__ __align__(16) float g_pool_avg[BATCH*S];
__device__ __align__(16) float g_y[BATCH*S];

// ---------------------------------------------------------------------------
// Kernel 1: full channel pooling in one kernel. Block = (batch, 16 s4 slab),
// 128 threads = 8 q-groups x 16 s4. Each thread reduces 32 channels (float4),
// then an smem tree folds the 8 q-groups. Writes final pooled max/avg (800KB)
// -- no partial round-trip through DRAM/L2.
// 1568 blocks x 128 thr: all resident, single wave.
// ---------------------------------------------------------------------------
__global__ void __launch_bounds__(128) pool_full(const float* __restrict__ x) {
    __shared__ float4 smx[128];
    __shared__ float4 ssm[128];

    const int blk  = blockIdx.x;          // 0..1567
    const int b    = blk / 49;            // 49 slabs per batch (49*16 = 784)
    const int sblk = blk % 49;
    const int t    = threadIdx.x;
    const int q    = t >> 4;              // 0..7  (32 channels each)
    const int s4   = sblk * 16 + (t & 15);

    const float4* p = reinterpret_cast<const float4*>(x)
                    + (size_t)(b * CHAN + q * 32) * S4 + s4;

    float4 mx0 = make_float4(-INFINITY, -INFINITY, -INFINITY, -INFINITY);
    float4 mx1 = mx0;
    float4 sm0 = make_float4(0.f, 0.f, 0.f, 0.f);
    float4 sm1 = sm0;

    #pragma unroll 8
    for (int c = 0; c < 32; c += 2) {
        float4 v0 = __ldcs(p + (size_t)c * S4);
        float4 v1 = __ldcs(p + (size_t)(c + 1) * S4);
        mx0.x = fmaxf(mx0.x, v0.x); mx0.y = fmaxf(mx0.y, v0.y);
        mx0.z = fmaxf(mx0.z, v0.z); mx0.w = fmaxf(mx0.w, v0.w);
        sm0.x += v0.x; sm0.y += v0.y; sm0.z += v0.z; sm0.w += v0.w;
        mx1.x = fmaxf(mx1.x, v1.x); mx1.y = fmaxf(mx1.y, v1.y);
        mx1.z = fmaxf(mx1.z, v1.z); mx1.w = fmaxf(mx1.w, v1.w);
        sm1.x += v1.x; sm1.y += v1.y; sm1.z += v1.z; sm1.w += v1.w;
    }
    smx[t] = make_float4(fmaxf(mx0.x, mx1.x), fmaxf(mx0.y, mx1.y),
                         fmaxf(mx0.z, mx1.z), fmaxf(mx0.w, mx1.w));
    ssm[t] = make_float4(sm0.x + sm1.x, sm0.y + sm1.y,
                         sm0.z + sm1.z, sm0.w + sm1.w);
    __syncthreads();

    if (t < 16) {
        float4 mx = smx[t];
        float4 sm = ssm[t];
        #pragma unroll
        for (int k = 1; k < 8; ++k) {
            float4 m = smx[t + k * 16];
            float4 s = ssm[t + k * 16];
            mx.x = fmaxf(mx.x, m.x); mx.y = fmaxf(mx.y, m.y);
            mx.z = fmaxf(mx.z, m.z); mx.w = fmaxf(mx.w, m.w);
            sm.x += s.x; sm.y += s.y; sm.z += s.z; sm.w += s.w;
        }
        const float inv = 1.0f / (float)CHAN;
        sm.x *= inv; sm.y *= inv; sm.z *= inv; sm.w *= inv;
        int o = b * S4 + sblk * 16 + t;
        reinterpret_cast<float4*>(g_pool_max)[o] = mx;
        reinterpret_cast<float4*>(g_pool_avg)[o] = sm;
    }
}

// ---------------------------------------------------------------------------
// Kernel 2 (fused middle): per batch -> load pooled maps, conv+sigmoid with
// pass-0 histogram fused in, exact radix select, masked write to g_y.
// One block per batch, 1024 threads.
// ---------------------------------------------------------------------------
__global__ void __launch_bounds__(1024, 1) fused_mid(const float* __restrict__ w) {
    __shared__ float pm[S];
    __shared__ float pa[S];
    __shared__ unsigned int uvals[S];     // sigmoid bits; >0 so uint order == float order
    __shared__ int hist[256];
    __shared__ float ws[18];
    __shared__ unsigned int s_prefix;
    __shared__ int s_r, s_less;
    __shared__ int tieIdx[256];
    __shared__ int tieCount;
    __shared__ int s_bound;

    const int b = blockIdx.x;
    const int t = threadIdx.x;
    const int lane = t & 31;

    if (t < 18) ws[t] = w[t];
    if (t < 256) hist[t] = 0;             // pre-clear for fused pass 0
    if (t == 0) { s_r = RNUM - 1; s_less = 0; s_prefix = 0u; tieCount = 0; }

    // --- load pooled max/avg (L2-hot, float4/thread) ---
    if (t < S4) {
        reinterpret_cast<float4*>(pm)[t] =
            reinterpret_cast<const float4*>(g_pool_max)[b * S4 + t];
        reinterpret_cast<float4*>(pa)[t] =
            reinterpret_cast<const float4*>(g_pool_avg)[b * S4 + t];
    }
    __syncthreads();

    // --- 3x3 conv (2ch->1ch, pad 1, cross-correlation OIHW) + sigmoid,
    //     pass-0 histogram (high 8 bits) fused in ---
    for (int i = t; i < S; i += 1024) {
        int oh = i / WW, ow = i % WW;
        float acc = 0.f;
        #pragma unroll
        for (int ky = 0; ky < 3; ++ky) {
            int ih = oh + ky - 1;
            if (ih < 0 || ih >= HH) continue;
            #pragma unroll
            for (int kx = 0; kx < 3; ++kx) {
                int iw = ow + kx - 1;
                if (iw < 0 || iw >= WW) continue;
                int ii = ih * WW + iw;
                acc = fmaf(pm[ii], ws[ky * 3 + kx], acc);
                acc = fmaf(pa[ii], ws[9 + ky * 3 + kx], acc);
            }
        }
        unsigned int u = __float_as_uint(1.0f / (1.0f + expf(-acc)));
        uvals[i] = u;
        atomicAdd(&hist[u >> 24], 1);
    }
    __syncthreads();

    // --- 4-pass radix select; pass-0 histogram already built above ---
    #pragma unroll
    for (int pass = 0; pass < 4; ++pass) {
        const int shift = 24 - 8 * pass;

        if (pass > 0) {
            const unsigned int pmask = 0xFFFFFFFFu << (32 - 8 * pass);
            const unsigned int pref  = s_prefix;
            for (int i = t; i < S; i += 1024) {
                unsigned int u = uvals[i];
                if ((u & pmask) == pref)
                    atomicAdd(&hist[(u >> shift) & 0xFF], 1);
            }
            __syncthreads();
        }

        if (t < 32) {                      // warp-0 bin scan + select
            int base = t * 8;
            int h0 = hist[base + 0], h1 = hist[base + 1];
            int h2 = hist[base + 2], h3 = hist[base + 3];
            int h4 = hist[base + 4], h5 = hist[base + 5];
            int h6 = hist[base + 6], h7 = hist[base + 7];
            int tot = h0 + h1 + h2 + h3 + h4 + h5 + h6 + h7;

            int ex = tot;                  // -> exclusive prefix of lane totals
            #pragma unroll
            for (int d = 1; d < 32; d <<= 1) {
                int n = __shfl_up_sync(0xFFFFFFFFu, ex, d);
                if (lane >= d) ex += n;
            }
            ex -= tot;

            int r = s_r;
            if (ex <= r && r < ex + tot) { // exactly one lane matches
                int cum = ex, bin = base;
                int hh[8] = {h0,h1,h2,h3,h4,h5,h6,h7};
                #pragma unroll
                for (int k = 0; k < 8; ++k) {
                    if (cum + hh[k] > r) { bin = base + k; break; }
                    cum += hh[k];
                }
                s_r      = r - cum;
                s_less  += cum;
                s_prefix = (pass == 0 ? 0u : s_prefix) | ((unsigned int)bin << shift);
            }
        }
        __syncthreads();

        if (pass < 3) {                    // clear for next pass
            if (t < 256) hist[t] = 0;
            __syncthreads();
        }
    }

    const unsigned int T = s_prefix;
    const int zeroTies = RNUM - s_less;    // # ties (==T) to zero, ascending index

    for (int i = t; i < S; i += 1024) {
        if (uvals[i] == T) {
            int p = atomicAdd(&tieCount, 1);
            if (p < 256) tieIdx[p] = i;
        }
    }
    __syncthreads();

    if (t == 0) {
        int tc = tieCount < 256 ? tieCount : 256;
        for (int i = 1; i < tc; ++i) {     // expected tc == 1
            int v2 = tieIdx[i], j = i - 1;
            while (j >= 0 && tieIdx[j] > v2) { tieIdx[j + 1] = tieIdx[j]; --j; }
            tieIdx[j + 1] = v2;
        }
        int z = zeroTies < tc ? zeroTies : tc;
        s_bound = (z <= 0) ? 0 : (tieIdx[z - 1] + 1);
    }
    __syncthreads();

    const int bound = s_bound;
    float* yb = g_y + b * S;
    for (int i = t; i < S; i += 1024) {
        unsigned int u = uvals[i];
        float v = __uint_as_float(u);
        if (u < T || (u == T && i < bound)) v = 0.0f;
        yb[i] = v;
    }
}

// ---------------------------------------------------------------------------
// Kernel 3: broadcast masked map to all 256 channels.
// 1 float4 load -> 8 channel stores per thread; 3136 blocks (full chip).
// ---------------------------------------------------------------------------
__global__ void __launch_bounds__(256) bcast(float* __restrict__ out) {
    int gid  = blockIdx.x * 256 + threadIdx.x;    // 0 .. BATCH*32*S4-1
    int s4   = gid % S4;
    int rowg = gid / S4;                          // b*32 + cg
    int b    = rowg >> 5;
    int cg   = rowg & 31;

    float4 v = __ldg(reinterpret_cast<const float4*>(g_y) + b * S4 + s4);

    float4* p = reinterpret_cast<float4*>(out)
              + ((size_t)(b * CHAN + cg * 8)) * S4 + s4;
    #pragma unroll
    for (int k = 0; k < 8; ++k) {
        *p = v;
        p += S4;
    }
}

// ---------------------------------------------------------------------------
extern "C" void kernel_launch(void* const* d_in, const int* in_sizes, int n_in,
                              void* d_out, int out_size) {
    const float* x = (const float*)d_in[0];   // [32,256,56,56]
    const float* w = (const float*)d_in[1];   // [1,2,3,3]
    float* out = (float*)d_out;               // [32,256,56,56]

    pool_full<<<BATCH * 49, 128>>>(x);                 // 1568 blocks
    fused_mid<<<BATCH, 1024>>>(w);                     // 32 blocks
    bcast<<<(BATCH * 32 * S4) / 256, 256>>>(out);      // 3136 blocks
}

// round 11
// speedup vs baseline: 1.0457x; 1.0457x over previous
#include <cuda_runtime.h>
#include <stdint.h>
#include <math.h>

#define BATCH 32
#define CHAN  256
#define HH    56
#define WW    56
#define S     (HH*WW)        // 3136
#define S4    (S/4)          // 784
#define QSPLIT 8
#define CQ    (CHAN/QSPLIT)  // 32
#define RNUM  1568           // removed_num = round(3136*0.5)

// scratch (no cudaMalloc allowed)
__device__ __align__(16) float g_part_max[QSPLIT*BATCH*S];
__device__ __align__(16) float g_part_sum[QSPLIT*BATCH*S];
__device__ __align__(16) float g_y[BATCH*S];

// ---------------------------------------------------------------------------
// Kernel 1: partial channel max/sum. 784 blocks x 256 threads. (R8 shape —
// empirically at this pattern's bandwidth ceiling: ~19us, 70% DRAM.)
// ---------------------------------------------------------------------------
__global__ void pool_partial(const float* __restrict__ x) {
    int gid = blockIdx.x * blockDim.x + threadIdx.x;
    int q   = gid / (BATCH * S4);
    int rem = gid % (BATCH * S4);
    int b   = rem / S4;
    int s4  = rem % S4;

    const float4* p = reinterpret_cast<const float4*>(x)
                    + (size_t)(b * CHAN + q * CQ) * S4 + s4;

    float4 mx = make_float4(-INFINITY, -INFINITY, -INFINITY, -INFINITY);
    float4 sm = make_float4(0.f, 0.f, 0.f, 0.f);

    #pragma unroll 8
    for (int c = 0; c < CQ; ++c) {
        float4 v = __ldcs(p + (size_t)c * S4);   // read-once: stream past L2
        mx.x = fmaxf(mx.x, v.x); mx.y = fmaxf(mx.y, v.y);
        mx.z = fmaxf(mx.z, v.z); mx.w = fmaxf(mx.w, v.w);
        sm.x += v.x; sm.y += v.y; sm.z += v.z; sm.w += v.w;
    }

    int o = (q * BATCH + b) * S4 + s4;
    reinterpret_cast<float4*>(g_part_max)[o] = mx;
    reinterpret_cast<float4*>(g_part_sum)[o] = sm;
}

// ---------------------------------------------------------------------------
// Kernel 2 (fused middle): combine partials, conv+sigmoid (pass-0 histogram
// fused), exact radix select, masked write (tie handling merged into the
// write sweep). One block per batch, 1024 threads.
// ---------------------------------------------------------------------------
__global__ void __launch_bounds__(1024, 1) fused_mid(const float* __restrict__ w) {
    __shared__ float pm[S];
    __shared__ float pa[S];
    __shared__ unsigned int uvals[S];     // sigmoid bits; >0 so uint order == float order
    __shared__ int hist[256];
    __shared__ float ws[18];
    __shared__ unsigned int s_prefix;
    __shared__ int s_r, s_less;
    __shared__ int tieIdx[256];
    __shared__ int tieCount;

    const int b = blockIdx.x;
    const int t = threadIdx.x;
    const int lane = t & 31;

    if (t < 18) ws[t] = w[t];
    if (t < 256) hist[t] = 0;             // pre-clear for fused pass 0
    if (t == 0) { s_r = RNUM - 1; s_less = 0; s_prefix = 0u; tieCount = 0; }

    // --- combine QSPLIT partials -> pooled max/avg in smem (float4/thread) ---
    const float inv = 1.0f / (float)CHAN;
    if (t < S4) {
        float4 mx = make_float4(-INFINITY, -INFINITY, -INFINITY, -INFINITY);
        float4 sm = make_float4(0.f, 0.f, 0.f, 0.f);
        #pragma unroll
        for (int q = 0; q < QSPLIT; ++q) {
            int o = (q * BATCH + b) * S4 + t;
            float4 m = reinterpret_cast<const float4*>(g_part_max)[o];
            float4 s = reinterpret_cast<const float4*>(g_part_sum)[o];
            mx.x = fmaxf(mx.x, m.x); mx.y = fmaxf(mx.y, m.y);
            mx.z = fmaxf(mx.z, m.z); mx.w = fmaxf(mx.w, m.w);
            sm.x += s.x; sm.y += s.y; sm.z += s.z; sm.w += s.w;
        }
        sm.x *= inv; sm.y *= inv; sm.z *= inv; sm.w *= inv;
        reinterpret_cast<float4*>(pm)[t] = mx;
        reinterpret_cast<float4*>(pa)[t] = sm;
    }
    __syncthreads();

    // --- conv 3x3 (2ch->1ch, pad 1, cross-corr OIHW) + sigmoid + pass-0 hist ---
    for (int i = t; i < S; i += 1024) {
        int oh = i / WW, ow = i % WW;
        float acc = 0.f;
        #pragma unroll
        for (int ky = 0; ky < 3; ++ky) {
            int ih = oh + ky - 1;
            if (ih < 0 || ih >= HH) continue;
            #pragma unroll
            for (int kx = 0; kx < 3; ++kx) {
                int iw = ow + kx - 1;
                if (iw < 0 || iw >= WW) continue;
                int ii = ih * WW + iw;
                acc = fmaf(pm[ii], ws[ky * 3 + kx], acc);
                acc = fmaf(pa[ii], ws[9 + ky * 3 + kx], acc);
            }
        }
        unsigned int u = __float_as_uint(1.0f / (1.0f + expf(-acc)));
        uvals[i] = u;
        atomicAdd(&hist[u >> 24], 1);      // fused radix pass 0
    }
    __syncthreads();

    // --- 4-pass radix select (pass 0 histogram already built) ---
    #pragma unroll
    for (int pass = 0; pass < 4; ++pass) {
        const int shift = 24 - 8 * pass;

        if (pass > 0) {
            const unsigned int pmask = 0xFFFFFFFFu << (32 - 8 * pass);
            const unsigned int pref  = s_prefix;
            for (int i = t; i < S; i += 1024) {
                unsigned int u = uvals[i];
                if ((u & pmask) == pref)
                    atomicAdd(&hist[(u >> shift) & 0xFF], 1);
            }
            __syncthreads();
        }

        if (t < 32) {                      // warp-0 bin scan + select
            int base = t * 8;
            int h0 = hist[base + 0], h1 = hist[base + 1];
            int h2 = hist[base + 2], h3 = hist[base + 3];
            int h4 = hist[base + 4], h5 = hist[base + 5];
            int h6 = hist[base + 6], h7 = hist[base + 7];
            int tot = h0 + h1 + h2 + h3 + h4 + h5 + h6 + h7;

            int ex = tot;                  // -> exclusive prefix of lane totals
            #pragma unroll
            for (int d = 1; d < 32; d <<= 1) {
                int n = __shfl_up_sync(0xFFFFFFFFu, ex, d);
                if (lane >= d) ex += n;
            }
            ex -= tot;

            int r = s_r;
            if (ex <= r && r < ex + tot) { // exactly one lane matches
                int cum = ex, bin = base;
                int hh[8] = {h0,h1,h2,h3,h4,h5,h6,h7};
                #pragma unroll
                for (int k = 0; k < 8; ++k) {
                    if (cum + hh[k] > r) { bin = base + k; break; }
                    cum += hh[k];
                }
                s_r      = r - cum;
                s_less  += cum;
                s_prefix = (pass == 0 ? 0u : s_prefix) | ((unsigned int)bin << shift);
            }
        }
        __syncthreads();

        if (pass < 3) {                    // clear for next pass
            if (t < 256) hist[t] = 0;
            __syncthreads();
        }
    }

    const unsigned int T = s_prefix;
    const int zeroTies = RNUM - s_less;    // # ties (==T) to zero, ascending index

    // --- merged masked write + tie collection (single sweep) ---
    float* yb = g_y + b * S;
    for (int i = t; i < S; i += 1024) {
        unsigned int u = uvals[i];
        float v = __uint_as_float(u);
        if (u < T) v = 0.0f;
        else if (u == T) {
            int p = atomicAdd(&tieCount, 1);
            if (p < 256) tieIdx[p] = i;
        }
        yb[i] = v;                         // ties written as value; fixed below
    }
    __syncthreads();

    if (t == 0) {
        int tc = tieCount < 256 ? tieCount : 256;
        for (int i = 1; i < tc; ++i) {     // expected tc == 1
            int v2 = tieIdx[i], j = i - 1;
            while (j >= 0 && tieIdx[j] > v2) { tieIdx[j + 1] = tieIdx[j]; --j; }
            tieIdx[j + 1] = v2;
        }
        int z = zeroTies < tc ? zeroTies : tc;
        for (int j = 0; j < z; ++j) yb[tieIdx[j]] = 0.0f;
    }
}

// ---------------------------------------------------------------------------
// Kernel 3: broadcast masked map to all 256 channels.
// 1 float4 load -> 8 streaming (__stcs) stores; 1568 blocks x 512 threads.
// ---------------------------------------------------------------------------
__global__ void __launch_bounds__(512) bcast(float* __restrict__ out) {
    int gid  = blockIdx.x * 512 + threadIdx.x;    // 0 .. BATCH*32*S4-1
    int s4   = gid % S4;
    int rowg = gid / S4;                          // b*32 + cg
    int b    = rowg >> 5;
    int cg   = rowg & 31;

    float4 v = __ldg(reinterpret_cast<const float4*>(g_y) + b * S4 + s4);

    float4* p = reinterpret_cast<float4*>(out)
              + ((size_t)(b * CHAN + cg * 8)) * S4 + s4;
    #pragma unroll
    for (int k = 0; k < 8; ++k) {
        __stcs(p, v);                      // evict-first: don't churn L2
        p += S4;
    }
}

// ---------------------------------------------------------------------------
extern "C" void kernel_launch(void* const* d_in, const int* in_sizes, int n_in,
                              void* d_out, int out_size) {
    const float* x = (const float*)d_in[0];   // [32,256,56,56]
    const float* w = (const float*)d_in[1];   // [1,2,3,3]
    float* out = (float*)d_out;               // [32,256,56,56]

    pool_partial<<<(QSPLIT * BATCH * S4) / 256, 256>>>(x);   // 784 blocks
    fused_mid<<<BATCH, 1024>>>(w);                           // 32 blocks
    bcast<<<(BATCH * 32 * S4) / 512, 512>>>(out);            // 1568 blocks
}